// round 2
// baseline (speedup 1.0000x reference)
#include <cuda_runtime.h>
#include <cstdint>
#include <cstddef>

#define NB 16
#define NS 2048
#define ND 1024
#define NM 256
#define NROWS (NB*NS)   // 32768

// ---------------- scratch (device globals: allocation-free) ----------------
__device__ float g_xm[(size_t)NROWS * NM];
__device__ float g_xf[(size_t)NROWS * NM];
__device__ float g_xu[(size_t)NROWS * NM];
__device__ float g_H [(size_t)NROWS * NM];

// ---------------- helpers ----------------
__device__ __forceinline__ uint32_t f2tf32(float x) {
    uint32_t r; asm("cvt.rna.tf32.f32 %0, %1;" : "=r"(r) : "f"(x)); return r;
}
__device__ __forceinline__ void mma_tf32(float c[4], const uint32_t a[4], const uint32_t b[2]) {
    asm volatile("mma.sync.aligned.m16n8k8.row.col.f32.tf32.tf32.f32 "
        "{%0,%1,%2,%3}, {%4,%5,%6,%7}, {%8,%9}, {%0,%1,%2,%3};"
        : "+f"(c[0]), "+f"(c[1]), "+f"(c[2]), "+f"(c[3])
        : "r"(a[0]), "r"(a[1]), "r"(a[2]), "r"(a[3]), "r"(b[0]), "r"(b[1]));
}
__device__ __forceinline__ uint32_t smem_u32(const void* p) {
    return (uint32_t)__cvta_generic_to_shared(p);
}

// =====================================================================
// GEMM: C[row, n] = sum_k A[row, k] * W[n, k]   (tf32 tensor cores)
// BM=128, BN=128, BK=16, 256 threads, 8 warps (4x2), warp tile 32x64
// MODE 0: A = X (K=1024), W in {Wi, Wf[:, :1024], Wu[:, :1024]}, N=768
//         epilogue: +bias, silu for xm; -> g_xm / g_xf / g_xu
// MODE 1: A = [X | H] (K=1280), W = Wo (ld 1280), N=1024
//         epilogue: + bo[n] + X[row, n]; -> out
// =====================================================================
template<int MODE>
__global__ void __launch_bounds__(256) gemm_kernel(
    const float* __restrict__ X,
    const float* __restrict__ Wi, const float* __restrict__ bi,
    const float* __restrict__ Wf, const float* __restrict__ bf,
    const float* __restrict__ Wu, const float* __restrict__ bu,
    const float* __restrict__ Wo, const float* __restrict__ bo,
    float* __restrict__ out)
{
    __shared__ uint32_t As[2][128][20];
    __shared__ uint32_t Bs[2][128][20];

    const int tid  = threadIdx.x;
    const int lane = tid & 31;
    const int warp = tid >> 5;
    const int wm   = warp >> 1;   // 0..3
    const int wn   = warp & 1;    // 0..1
    const int bm   = blockIdx.x;
    const int bn   = blockIdx.y;
    const int row0 = bm * 128;
    const int col0 = bn * 128;

    const float* Bmat; int ldb; int K; int nbase;
    const float* bias = bi; float* dst = g_xm; int seg = 0;
    if (MODE == 0) {
        K = 1024;
        seg = bn >> 1;
        Bmat = (seg == 0) ? Wi : ((seg == 1) ? Wf : Wu);
        ldb  = (seg == 0) ? 1024 : 1280;
        nbase = (bn & 1) * 128;
        bias = (seg == 0) ? bi : ((seg == 1) ? bf : bu);
        dst  = (seg == 0) ? g_xm : ((seg == 1) ? g_xf : g_xu);
    } else {
        K = 1280; Bmat = Wo; ldb = 1280; nbase = col0;
    }
    const int NKT = K / 16;

    const int lr = tid >> 2;        // 0..63
    const int lc = (tid & 3) * 4;   // 0,4,8,12

    float acc[2][8][4];
    #pragma unroll
    for (int i = 0; i < 2; i++)
        #pragma unroll
        for (int j = 0; j < 8; j++)
            #pragma unroll
            for (int k = 0; k < 4; k++) acc[i][j][k] = 0.f;

    float4 ra[2], rb[2];

    // ---- global loaders ----
    auto ldgA = [&](int kt) {
        const int kk = kt * 16 + lc;
        #pragma unroll
        for (int h = 0; h < 2; ++h) {
            const int rr = row0 + lr + h * 64;
            if (MODE == 1 && kk >= 1024)
                ra[h] = *(const float4*)(g_H + (size_t)rr * NM + (kk - 1024));
            else
                ra[h] = *(const float4*)(X + (size_t)rr * ND + kk);
        }
    };
    auto ldgB = [&](int kt) {
        const int kk = kt * 16 + lc;
        #pragma unroll
        for (int h = 0; h < 2; ++h) {
            const int rr = nbase + lr + h * 64;
            rb[h] = *(const float4*)(Bmat + (size_t)rr * ldb + kk);
        }
    };
    auto stsAB = [&](int buf) {
        #pragma unroll
        for (int h = 0; h < 2; ++h) {
            uint32_t* pa = &As[buf][lr + h * 64][lc];
            pa[0] = f2tf32(ra[h].x); pa[1] = f2tf32(ra[h].y);
            pa[2] = f2tf32(ra[h].z); pa[3] = f2tf32(ra[h].w);
            uint32_t* pb = &Bs[buf][lr + h * 64][lc];
            pb[0] = f2tf32(rb[h].x); pb[1] = f2tf32(rb[h].y);
            pb[2] = f2tf32(rb[h].z); pb[3] = f2tf32(rb[h].w);
        }
    };
    auto compute = [&](int buf) {
        #pragma unroll
        for (int ks = 0; ks < 2; ++ks) {
            const int k0 = ks * 8 + (lane & 3);
            uint32_t a[2][4]; uint32_t bb[8][2];
            #pragma unroll
            for (int mf = 0; mf < 2; ++mf) {
                const int r = wm * 32 + mf * 16 + (lane >> 2);
                a[mf][0] = As[buf][r    ][k0];
                a[mf][1] = As[buf][r + 8][k0];
                a[mf][2] = As[buf][r    ][k0 + 4];
                a[mf][3] = As[buf][r + 8][k0 + 4];
            }
            #pragma unroll
            for (int nf = 0; nf < 8; ++nf) {
                const int c = wn * 64 + nf * 8 + (lane >> 2);
                bb[nf][0] = Bs[buf][c][k0];
                bb[nf][1] = Bs[buf][c][k0 + 4];
            }
            #pragma unroll
            for (int mf = 0; mf < 2; ++mf)
                #pragma unroll
                for (int nf = 0; nf < 8; ++nf)
                    mma_tf32(acc[mf][nf], a[mf], bb[nf]);
        }
    };

    // ---- main loop (double buffered) ----
    ldgA(0); ldgB(0);
    stsAB(0);
    __syncthreads();
    for (int kt = 0; kt < NKT; ++kt) {
        const int buf = kt & 1;
        if (kt + 1 < NKT) { ldgA(kt + 1); ldgB(kt + 1); }
        compute(buf);
        if (kt + 1 < NKT) stsAB(buf ^ 1);
        __syncthreads();
    }

    // ---- epilogue ----
    #pragma unroll
    for (int mf = 0; mf < 2; ++mf)
        #pragma unroll
        for (int nf = 0; nf < 8; ++nf)
            #pragma unroll
            for (int h = 0; h < 2; ++h) {
                const int row = row0 + wm * 32 + mf * 16 + (lane >> 2) + h * 8;
                const int c0  = col0 + wn * 64 + nf * 8 + (lane & 3) * 2;
                float v0 = acc[mf][nf][h * 2 + 0];
                float v1 = acc[mf][nf][h * 2 + 1];
                if (MODE == 0) {
                    const int cl = c0 & 255;
                    v0 += bias[cl]; v1 += bias[cl + 1];
                    if (seg == 0) {
                        v0 = v0 / (1.f + __expf(-v0));
                        v1 = v1 / (1.f + __expf(-v1));
                    }
                    *(float2*)&dst[(size_t)row * NM + cl] = make_float2(v0, v1);
                } else {
                    v0 += bo[c0]     + X[(size_t)row * ND + c0];
                    v1 += bo[c0 + 1] + X[(size_t)row * ND + c0 + 1];
                    *(float2*)&out[(size_t)row * ND + c0] = make_float2(v0, v1);
                }
            }
}

// =====================================================================
// Recurrence: 16 clusters of 8 CTAs (one cluster per batch).
// CTA `slice` owns j in [slice*32, slice*32+32). 256 threads, 8 warps:
//   warp w: g = w&1 (0: f via WfH, 1: u via WuH), q = w>>1 (k-quarter).
// Weights in registers (64 floats/thread). h double-buffered in smem,
// broadcast to all 8 cluster CTAs via st.shared::cluster each step.
// =====================================================================
__global__ void __cluster_dims__(8, 1, 1) __launch_bounds__(256)
recur_kernel(const float* __restrict__ Wf, const float* __restrict__ Wu,
             float* __restrict__ hfinal)
{
    const int tid   = threadIdx.x;
    const int lane  = tid & 31;
    const int w     = tid >> 5;
    const int g     = w & 1;
    const int q     = w >> 1;
    const int slice = blockIdx.x & 7;
    const int b     = blockIdx.x >> 3;
    const int j     = slice * 32 + lane;
    const int k0    = q * 64;

    __shared__ alignas(16) float h_sm[2][256];
    __shared__ float part[2][3][32];
    __shared__ float xf_s[2][32], xu_s[2][32], xm_s[2][32];
    __shared__ float u_s[32];

    // ---- load recurrent weights into registers ----
    float wreg[64];
    {
        const float* Wsrc = g ? Wu : Wf;
        const float* p = Wsrc + (size_t)j * 1280 + 1024 + k0;
        #pragma unroll
        for (int i = 0; i < 16; ++i) {
            float4 v = *(const float4*)(p + i * 4);
            wreg[4*i+0] = v.x; wreg[4*i+1] = v.y;
            wreg[4*i+2] = v.z; wreg[4*i+3] = v.w;
        }
    }

    // per-thread streaming base: (b*NS + t)*NM + slice*32 + lane
    const size_t bb0 = (size_t)b * NS * NM + slice * 32 + lane;

    // ---- init ----
    if (tid < 256) h_sm[0][tid] = 0.f;
    if (w == 2) xf_s[0][lane] = g_xf[bb0];
    if (w == 3) xu_s[0][lane] = g_xu[bb0];
    if (w == 4) xm_s[0][lane] = g_xm[bb0];
    __syncthreads();
    asm volatile("barrier.cluster.arrive.aligned;" ::: "memory");
    asm volatile("barrier.cluster.wait.aligned;"   ::: "memory");

    int p = 0;
    for (int t = 0; t < NS; ++t) {
        // prefetch t+1 (clamped) — latency hidden behind compute
        float pf = 0.f;
        {
            const int tt = (t + 1 < NS) ? (t + 1) : t;
            if (w == 2)      pf = g_xf[bb0 + (size_t)tt * NM];
            else if (w == 3) pf = g_xu[bb0 + (size_t)tt * NM];
            else if (w == 4) pf = g_xm[bb0 + (size_t)tt * NM];
        }

        // ---- dot: acc = sum_k wreg[k] * h[k0+k], k in [0,64) ----
        float a0 = 0.f, a1 = 0.f, a2 = 0.f, a3 = 0.f;
        const float4* hv4 = (const float4*)(&h_sm[p][k0]);
        #pragma unroll
        for (int i = 0; i < 16; ++i) {
            const float4 hv = hv4[i];          // broadcast LDS.128
            a0 = fmaf(wreg[4*i+0], hv.x, a0);
            a1 = fmaf(wreg[4*i+1], hv.y, a1);
            a2 = fmaf(wreg[4*i+2], hv.z, a2);
            a3 = fmaf(wreg[4*i+3], hv.w, a3);
        }
        const float acc = (a0 + a1) + (a2 + a3);

        if (q > 0) part[g][q - 1][lane] = acc;
        __syncthreads();

        float fval = 0.f;
        if (q == 0) {
            const float tot = acc + part[g][0][lane] + part[g][1][lane] + part[g][2][lane];
            const float z = (g ? xu_s : xf_s)[p][lane] + tot;
            const float sg = 1.f / (1.f + __expf(-z));
            if (g) u_s[lane] = sg; else fval = sg;
        }
        __syncthreads();

        if (w == 0) {
            const float hn = fval * h_sm[p][j] + u_s[lane] * xm_s[p][lane];
            g_H[bb0 + (size_t)t * NM] = hn;
            if (t == NS - 1 && hfinal) hfinal[b * NM + j] = hn;
            // broadcast owned h slice to all 8 cluster CTAs (incl. self)
            const uint32_t la = smem_u32(&h_sm[p ^ 1][j]);
            #pragma unroll
            for (int r = 0; r < 8; ++r) {
                asm volatile(
                    "{\n\t.reg .b32 ra;\n\t"
                    "mapa.shared::cluster.u32 ra, %0, %1;\n\t"
                    "st.shared::cluster.f32 [ra], %2;\n\t}"
                    :: "r"(la), "r"(r), "f"(hn));
            }
        }
        // stage prefetched inputs for t+1
        if (w == 2)      xf_s[p ^ 1][lane] = pf;
        else if (w == 3) xu_s[p ^ 1][lane] = pf;
        else if (w == 4) xm_s[p ^ 1][lane] = pf;

        asm volatile("barrier.cluster.arrive.aligned;" ::: "memory");
        asm volatile("barrier.cluster.wait.aligned;"   ::: "memory");
        p ^= 1;
    }
}

// =====================================================================
extern "C" void kernel_launch(void* const* d_in, const int* in_sizes, int n_in,
                              void* d_out, int out_size)
{
    const float* x  = (const float*)d_in[0];
    const float* Wi = (const float*)d_in[1];
    const float* bi = (const float*)d_in[2];
    const float* Wf = (const float*)d_in[3];
    const float* bf = (const float*)d_in[4];
    const float* Wu = (const float*)d_in[5];
    const float* bu = (const float*)d_in[6];
    const float* Wo = (const float*)d_in[7];
    const float* bo = (const float*)d_in[8];
    float* out = (float*)d_out;

    // Phase 1: xm / xf / xu projections (tf32 tensor cores)
    gemm_kernel<0><<<dim3(NROWS / 128, 6), 256>>>(x, Wi, bi, Wf, bf, Wu, bu, Wo, bo, out);

    // Phase 2: sequential recurrence (16 batches x 8-CTA clusters)
    float* hfinal = nullptr;
    if ((long long)out_size >= (long long)NROWS * ND + (long long)NB * NM)
        hfinal = out + (size_t)NROWS * ND;
    recur_kernel<<<128, 256>>>(Wf, Wu, hfinal);

    // Phase 3: out = x + bo + [X | H] @ Wo^T
    gemm_kernel<1><<<dim3(NROWS / 128, 8), 256>>>(x, Wi, bi, Wf, bf, Wu, bu, Wo, bo, out);
}